// round 10
// baseline (speedup 1.0000x reference)
#include <cuda_runtime.h>
#include <cuda_fp16.h>
#include <math.h>
#include <stdint.h>

#define N_ 4
#define C_ 128
#define COUT_ 128
#define H_ 96
#define W_ 96
#define HW_ (H_*W_)
#define GN_GROUPS_ 8
#define GN_EPS_ 1e-5f
#define CNT_PER_GROUP_ (16.0f*HW_)

// dcn region: 8 rows x 16 cols of pixels (N=128), M=128, K=1152
#define TILEH_ 8
#define TILEW_ 16
#define NREG_ 72            // (96/8)*(96/16)
#define WR_ 12
#define WC_ 20
#define WWORDS_ 240         // WR_*WC_ half2 words per channel
#define SROW_ 21            // samp row stride in uint32 words (42 halves)

// dynamic smem map (bytes) for k_dcn
#define SM_BIDX  0          // 9*128*2 = 2304
#define SM_WGT   2304       // 9*128*16 = 18432 -> 20736
#define SM_RED   20736      // 256 -> 20992
#define SM_WIN2  20992      // 32*240*4 = 30720 -> 51712
#define SM_SAMP0 51712      // 128*21*4 = 10752 -> 62464
#define SM_SAMP1 62464      // 10752 -> 73216
#define SM_TOT   73216

// ---------------- scratch ----------------
__device__ float    g_dx[N_*HW_];
__device__ float    g_dy[N_*HW_];
__device__ float    g_mask[N_*HW_];
__device__ uint4    g_wA[36*512];                // A-fragment-ordered fp16 weights (294KB)
__device__ float    g_part[N_*GN_GROUPS_*NREG_*2];
__device__ float    g_stats[N_*GN_GROUPS_*2];

// ---------------- helpers ----------------
__device__ __forceinline__ void mma16816(float* d, uint32_t a0, uint32_t a1,
                                         uint32_t a2, uint32_t a3,
                                         uint32_t b0, uint32_t b1) {
    asm volatile("mma.sync.aligned.m16n8k16.row.col.f32.f16.f16.f32 "
                 "{%0,%1,%2,%3}, {%4,%5,%6,%7}, {%8,%9}, {%0,%1,%2,%3};"
                 : "+f"(d[0]), "+f"(d[1]), "+f"(d[2]), "+f"(d[3])
                 : "r"(a0), "r"(a1), "r"(a2), "r"(a3), "r"(b0), "r"(b1));
}
__device__ __forceinline__ uint32_t packh2(float a, float b) {
    __half2 h = __floats2half2_rn(a, b);
    return *(uint32_t*)&h;
}

// ---------------- kernel 1: head conv + weight prep (merged) ----------------
// blocks [0,144): head conv 16x16 tiles; blocks [144,216): A-fragment weight prep
__global__ __launch_bounds__(256) void k_prep(const float* __restrict__ x,
                                              const float* __restrict__ w_head,
                                              const float* __restrict__ b_head,
                                              const float* __restrict__ w_dcn) {
    __shared__ float4 whf4[C_*9];     // [c][k] -> (w0,w1,w2,0)
    __shared__ float  win[8*324];

    int tid = threadIdx.x;
    int bx  = blockIdx.x;

    if (bx >= 144) {
        // ---- weight prep: t indexes [ci][sub][wm][mt][lane] ----
        int t = (bx - 144) * 256 + tid;     // 0..18431
        int lane = t & 31;
        int mt  = (t >> 5) & 3;
        int wm  = (t >> 7) & 1;
        int sub = (t >> 8) & 1;
        int ci  = t >> 9;                   // 0..35
        int cg = ci / 9, kk = ci % 9;
        int g = lane >> 2, tg = lane & 3;
        int o  = wm*64 + mt*16 + g;
        int c0 = cg*32 + sub*16 + 2*tg;
        uint4 u;
        u.x = packh2(w_dcn[o*1152 + c0*9 + kk],       w_dcn[o*1152 + (c0+1)*9 + kk]);
        u.y = packh2(w_dcn[(o+8)*1152 + c0*9 + kk],   w_dcn[(o+8)*1152 + (c0+1)*9 + kk]);
        u.z = packh2(w_dcn[o*1152 + (c0+8)*9 + kk],   w_dcn[o*1152 + (c0+9)*9 + kk]);
        u.w = packh2(w_dcn[(o+8)*1152 + (c0+8)*9 + kk], w_dcn[(o+8)*1152 + (c0+9)*9 + kk]);
        g_wA[t] = u;
        return;
    }

    // ---- head conv ----
    int n   = bx / 36;
    int t   = bx % 36;
    int by0 = (t / 6) * 16;
    int bx0 = (t % 6) * 16;

    for (int i = tid; i < C_*9; i += 256) {
        int c = i / 9, k = i % 9;
        whf4[i] = make_float4(w_head[(0*C_ + c)*9 + k],
                              w_head[(1*C_ + c)*9 + k],
                              w_head[(2*C_ + c)*9 + k], 0.f);
    }

    int ly = tid / 16, lx = tid % 16;
    float h0 = 0.f, h1 = 0.f, h2 = 0.f;

    for (int c0 = 0; c0 < C_; c0 += 8) {
        __syncthreads();
        for (int i = tid; i < 8*324; i += 256) {
            int cb = i / 324;
            int r  = (i % 324) / 18, cc = (i % 324) % 18;
            int gy = by0 - 1 + r, gx = bx0 - 1 + cc;
            float v = 0.f;
            if (gy >= 0 && gy < H_ && gx >= 0 && gx < W_)
                v = x[((n*C_ + c0 + cb)*H_ + gy)*W_ + gx];
            win[i] = v;
        }
        __syncthreads();
        #pragma unroll
        for (int cb = 0; cb < 8; cb++) {
            int c = c0 + cb;
            #pragma unroll
            for (int k = 0; k < 9; k++) {
                int ky = k / 3, kx = k % 3;
                float v = win[cb*324 + (ly + ky)*18 + lx + kx];
                float4 wv = whf4[c*9 + k];
                h0 += v * wv.x;
                h1 += v * wv.y;
                h2 += v * wv.z;
            }
        }
    }
    h0 += b_head[0]; h1 += b_head[1]; h2 += b_head[2];

    int gy = by0 + ly, gx = bx0 + lx;
    int pix = n*HW_ + gy*W_ + gx;
    g_dx[pix]   = 0.25f * tanhf(h0);
    g_dy[pix]   = 0.25f * tanhf(h1);
    g_mask[pix] = 1.f / (1.f + expf(-h2));
}

// ---------------- kernel 2: deformable sampling + fp16 warp-MMA GEMM ----------------
// grid: N*72 blocks, 256 threads (8 warps = 2 M-halves x 4 N-quarters).
// A frags read directly from g_wA (no smem staging); sampW double-buffered ->
// exactly one __syncthreads per tap.
__global__ __launch_bounds__(256, 2) void k_dcn(const float* __restrict__ x,
                                                float* __restrict__ out) {
    extern __shared__ char smem[];
    short*    bidx  = (short*)(smem + SM_BIDX);
    float4*   wgt   = (float4*)(smem + SM_WGT);
    float*    red   = (float*)(smem + SM_RED);
    __half2*  win2  = (__half2*)(smem + SM_WIN2);   // [c][r*20+x] = (v[x], v[x+1])
    uint32_t* sampB[2] = { (uint32_t*)(smem + SM_SAMP0), (uint32_t*)(smem + SM_SAMP1) };

    int tid = threadIdx.x, w = tid >> 5, lane = tid & 31;
    int g = lane >> 2, tg = lane & 3;
    int wm = w >> 2, ng = w & 3;
    int n0w = ng * 32;
    int bx = blockIdx.x;
    int n   = bx / NREG_;
    int reg = bx % NREG_;
    int ty0 = (reg / 6) * TILEH_;
    int tx0 = (reg % 6) * TILEW_;
    int wy0 = ty0 - 2, wx0 = tx0 - 2;

    // ---- bilinear tables: 128 px x 9 taps (mask folded) ----
    if (tid < 128) {
        int p  = tid;
        int ly = p >> 4, lx = p & 15;
        int gy = ty0 + ly, gx = tx0 + lx;
        int pix = n*HW_ + gy*W_ + gx;
        float dx = g_dx[pix], dy = g_dy[pix], m = g_mask[pix];
        const float syc[9] = {0,0,0, 1,0,-1, 1,1,-1};
        const float sxc[9] = {0,1,-1, 0,0,0, 1,-1,1};
        #pragma unroll
        for (int k = 0; k < 9; k++) {
            int ky = k / 3, kx = k % 3;
            float py = (float)(gy + ky - 1) + syc[k]*dx;
            float px = (float)(gx + kx - 1) + sxc[k]*dy;
            float fy0 = floorf(py), fx0 = floorf(px);
            int y0 = (int)fy0, x0 = (int)fx0;
            float fy = py - fy0, fx = px - fx0;
            float v00 = (y0   >= 0 && y0   < H_ && x0   >= 0 && x0   < W_) ? 1.f : 0.f;
            float v01 = (y0   >= 0 && y0   < H_ && x0+1 >= 0 && x0+1 < W_) ? 1.f : 0.f;
            float v10 = (y0+1 >= 0 && y0+1 < H_ && x0   >= 0 && x0   < W_) ? 1.f : 0.f;
            float v11 = (y0+1 >= 0 && y0+1 < H_ && x0+1 >= 0 && x0+1 < W_) ? 1.f : 0.f;
            float4 w4;
            w4.x = (1.f-fy)*(1.f-fx)*v00*m;
            w4.y = (1.f-fy)*fx      *v01*m;
            w4.z = fy      *(1.f-fx)*v10*m;
            w4.w = fy      *fx      *v11*m;
            int ly0 = min(max(y0 - wy0, 0), WR_-2);
            int lx0 = min(max(x0 - wx0, 0), WC_-2);
            bidx[k*128 + p] = (short)(ly0*WC_ + lx0);
            wgt[k*128 + p]  = w4;
        }
    }

    float acc[4][4][4];
    #pragma unroll
    for (int a = 0; a < 4; a++)
        #pragma unroll
        for (int b = 0; b < 4; b++)
            #pragma unroll
            for (int r = 0; r < 4; r++) acc[a][b][r] = 0.f;

    int sp  = tid & 127;                // sampling pixel
    int sc0 = (tid >> 7) * 16;          // sampling channel half (0 or 16)
    const uint4* aTbase = g_wA + wm*128 + lane;   // + ci*512 + sub*256 + mt*32

    for (int cg = 0; cg < 4; cg++) {
        // win2 overwrite safe: all sampling of prev cg completed before its tap-8
        // barrier; MMA after that barrier reads only sampW. (iter0: tables above
        // covered by the barrier below.)
        for (int i = tid; i < 32*WWORDS_; i += 256) {
            int c = i / WWORDS_;
            int rem = i % WWORDS_;
            int r = rem / WC_, xx = rem % WC_;
            int gy = wy0 + r, gx = wx0 + xx;
            float v0 = 0.f, v1 = 0.f;
            if (gy >= 0 && gy < H_) {
                const float* row = x + ((n*C_ + cg*32 + c)*H_ + gy)*W_;
                if (gx >= 0 && gx < W_)       v0 = row[gx];
                if (gx+1 >= 0 && gx+1 < W_)   v1 = row[gx+1];
            }
            win2[i] = __floats2half2_rn(v0, v1);
        }
        __syncthreads();

        for (int k = 0; k < 9; k++) {
            int ci = cg*9 + k;
            int b  = ci & 1;
            uint32_t* sampW = sampB[b];
            const uint4* aT = aTbase + ci*512;

            // ---- prefetch sub0 A frags (L1/L2; latency hidden by sampling) ----
            uint4 a0[4];
            #pragma unroll
            for (int mt = 0; mt < 4; mt++) a0[mt] = aT[mt*32];

            // ---- sampling -> sampW[b] (fp16 pairs) ----
            {
                int base = bidx[k*128 + sp];
                float4 w4 = wgt[k*128 + sp];
                #pragma unroll
                for (int j = 0; j < 16; j += 2) {
                    int c = sc0 + j;
                    float2 c0a = __half22float2(win2[c*WWORDS_ + base]);
                    float2 c0b = __half22float2(win2[c*WWORDS_ + base + WC_]);
                    float s0 = w4.x*c0a.x + w4.y*c0a.y + w4.z*c0b.x + w4.w*c0b.y;
                    float2 c1a = __half22float2(win2[(c+1)*WWORDS_ + base]);
                    float2 c1b = __half22float2(win2[(c+1)*WWORDS_ + base + WC_]);
                    float s1 = w4.x*c1a.x + w4.y*c1a.y + w4.z*c1b.x + w4.w*c1b.y;
                    sampW[sp*SROW_ + (c >> 1)] = packh2(s0, s1);
                }
            }
            __syncthreads();   // the ONLY barrier per tap

            // ---- prefetch sub1 A frags (hidden under sub0 MMAs) ----
            uint4 a1[4];
            #pragma unroll
            for (int mt = 0; mt < 4; mt++) a1[mt] = aT[256 + mt*32];

            // ---- MMA sub0 ----
            {
                uint32_t b0[4], b1[4];
                #pragma unroll
                for (int nt = 0; nt < 4; nt++) {
                    int px = n0w + nt*8 + g;
                    b0[nt] = sampW[px*SROW_ + tg];
                    b1[nt] = sampW[px*SROW_ + tg + 4];
                }
                #pragma unroll
                for (int mt = 0; mt < 4; mt++)
                    #pragma unroll
                    for (int nt = 0; nt < 4; nt++)
                        mma16816(acc[mt][nt], a0[mt].x, a0[mt].y, a0[mt].z, a0[mt].w,
                                 b0[nt], b1[nt]);
            }
            // ---- MMA sub1 ----
            {
                uint32_t b0[4], b1[4];
                #pragma unroll
                for (int nt = 0; nt < 4; nt++) {
                    int px = n0w + nt*8 + g;
                    b0[nt] = sampW[px*SROW_ + 8 + tg];
                    b1[nt] = sampW[px*SROW_ + 8 + tg + 4];
                }
                #pragma unroll
                for (int mt = 0; mt < 4; mt++)
                    #pragma unroll
                    for (int nt = 0; nt < 4; nt++)
                        mma16816(acc[mt][nt], a1[mt].x, a1[mt].y, a1[mt].z, a1[mt].w,
                                 b0[nt], b1[nt]);
            }
            // no barrier here: next tap writes the other samp buffer
        }
    }

    // ---- epilogue: stores + GN partials ----
    float s4[4] = {0,0,0,0}, q4[4] = {0,0,0,0};
    #pragma unroll
    for (int mt = 0; mt < 4; mt++) {
        int o1 = wm*64 + mt*16 + g;
        #pragma unroll
        for (int nt = 0; nt < 4; nt++) {
            int p  = n0w + nt*8 + 2*tg;
            int gy = ty0 + (p >> 4), gx = tx0 + (p & 15);
            float2 lo = make_float2(acc[mt][nt][0], acc[mt][nt][1]);
            float2 hi = make_float2(acc[mt][nt][2], acc[mt][nt][3]);
            *(float2*)&out[((n*COUT_ + o1    )*H_ + gy)*W_ + gx] = lo;
            *(float2*)&out[((n*COUT_ + o1 + 8)*H_ + gy)*W_ + gx] = hi;
            #pragma unroll
            for (int r = 0; r < 4; r++) {
                float v = acc[mt][nt][r];
                s4[mt] += v; q4[mt] += v*v;
            }
        }
    }
    #pragma unroll
    for (int mt = 0; mt < 4; mt++) {
        #pragma unroll
        for (int o = 16; o; o >>= 1) {
            s4[mt] += __shfl_xor_sync(0xFFFFFFFFu, s4[mt], o);
            q4[mt] += __shfl_xor_sync(0xFFFFFFFFu, q4[mt], o);
        }
    }
    if (lane == 0) {
        #pragma unroll
        for (int mt = 0; mt < 4; mt++) {
            red[w*4 + mt]      = s4[mt];
            red[32 + w*4 + mt] = q4[mt];
        }
    }
    __syncthreads();
    if (tid < 8) {                    // group gid = wm*4+mt
        int gwm = tid >> 2, gmt = tid & 3;
        float s = 0.f, q = 0.f;
        #pragma unroll
        for (int j = 0; j < 4; j++) {
            s += red[(gwm*4 + j)*4 + gmt];
            q += red[32 + (gwm*4 + j)*4 + gmt];
        }
        int base = (((n*GN_GROUPS_ + tid)*NREG_) + reg)*2;
        g_part[base + 0] = s;
        g_part[base + 1] = q;
    }
}

// ---------------- kernel 3: GN stats reduce ----------------
__global__ void k_gnreduce(void) {
    int b = blockIdx.x;
    int lane = threadIdx.x;
    float s = 0.f, q = 0.f;
    for (int i = lane; i < NREG_; i += 32) {
        s += g_part[(b*NREG_ + i)*2 + 0];
        q += g_part[(b*NREG_ + i)*2 + 1];
    }
    #pragma unroll
    for (int o = 16; o; o >>= 1) {
        s += __shfl_xor_sync(0xFFFFFFFFu, s, o);
        q += __shfl_xor_sync(0xFFFFFFFFu, q, o);
    }
    if (lane == 0) {
        float inv = 1.f / CNT_PER_GROUP_;
        float mean = s * inv;
        float var  = q * inv - mean*mean;
        g_stats[b*2 + 0] = mean;
        g_stats[b*2 + 1] = rsqrtf(var + GN_EPS_);
    }
}

// ---------------- kernel 4: normalize + affine + relu (4x float4 per thread) ----------------
__global__ __launch_bounds__(256) void k_apply(float* __restrict__ out,
                                               const float* __restrict__ gamma,
                                               const float* __restrict__ beta) {
    int t0 = blockIdx.x * 1024 + threadIdx.x;   // float4 index base
    #pragma unroll
    for (int u = 0; u < 4; u++) {
        int i4 = t0 + u*256;
        if (i4 >= N_*COUT_*HW_/4) break;
        int i = i4 * 4;
        int c = (i / HW_) % COUT_;
        int n = i / (HW_*COUT_);
        int g = c >> 4;
        float mean = g_stats[(n*GN_GROUPS_ + g)*2 + 0];
        float rstd = g_stats[(n*GN_GROUPS_ + g)*2 + 1];
        float sc = rstd * gamma[c];
        float sh = beta[c] - mean * sc;
        float4 v = ((float4*)out)[i4];
        v.x = fmaxf(v.x*sc + sh, 0.f);
        v.y = fmaxf(v.y*sc + sh, 0.f);
        v.z = fmaxf(v.z*sc + sh, 0.f);
        v.w = fmaxf(v.w*sc + sh, 0.f);
        ((float4*)out)[i4] = v;
    }
}

extern "C" void kernel_launch(void* const* d_in, const int* in_sizes, int n_in,
                              void* d_out, int out_size) {
    const float* x       = (const float*)d_in[0];
    const float* w_head  = (const float*)d_in[1];
    const float* b_head  = (const float*)d_in[2];
    const float* w_dcn   = (const float*)d_in[3];
    const float* gamma   = (const float*)d_in[4];
    const float* beta    = (const float*)d_in[5];
    float* out = (float*)d_out;

    cudaFuncSetAttribute(k_dcn, cudaFuncAttributeMaxDynamicSharedMemorySize, SM_TOT);

    k_prep<<<216, 256>>>(x, w_head, b_head, w_dcn);
    k_dcn<<<N_*NREG_, 256, SM_TOT>>>(x, out);
    k_gnreduce<<<N_*GN_GROUPS_, 32>>>();
    k_apply<<<(N_*COUT_*HW_/4 + 1023)/1024, 256>>>(out, gamma, beta);
}

// round 12
// speedup vs baseline: 1.0140x; 1.0140x over previous
#include <cuda_runtime.h>
#include <cuda_fp16.h>
#include <math.h>
#include <stdint.h>

#define N_ 4
#define C_ 128
#define COUT_ 128
#define H_ 96
#define W_ 96
#define HW_ (H_*W_)
#define GN_GROUPS_ 8
#define GN_EPS_ 1e-5f
#define CNT_PER_GROUP_ (16.0f*HW_)

// dcn region: 8 rows x 16 cols of pixels (N=128), M=128, K=1152
#define TILEH_ 8
#define TILEW_ 16
#define NREG_ 72            // (96/8)*(96/16)
#define WR_ 12
#define WC_ 20
#define WWORDS_ 240         // WR_*WC_ half2 words per channel
#define SROW_ 21            // samp row stride in uint32 words (42 halves)

// dynamic smem map (bytes) for k_dcn
#define SM_BIDX  0          // 2304
#define SM_WGT   2304       // 18432 -> 20736
#define SM_RED   20736      // 256 -> 20992
#define SM_WIN2  20992      // 30720 -> 51712
#define SM_SAMP0 51712      // 10752 -> 62464
#define SM_SAMP1 62464      // 10752 -> 73216
#define SM_ASM0  73216      // 8192 -> 81408
#define SM_ASM1  81408      // 8192 -> 89600
#define SM_TOT   89600

// ---------------- scratch ----------------
__device__ float    g_dx[N_*HW_];
__device__ float    g_dy[N_*HW_];
__device__ float    g_mask[N_*HW_];
__device__ uint4    g_wA[36*512];                // A-fragment-ordered fp16 weights (294KB)
__device__ float    g_part[N_*GN_GROUPS_*NREG_*2];

// ---------------- helpers ----------------
__device__ __forceinline__ void mma16816(float* d, uint32_t a0, uint32_t a1,
                                         uint32_t a2, uint32_t a3,
                                         uint32_t b0, uint32_t b1) {
    asm volatile("mma.sync.aligned.m16n8k16.row.col.f32.f16.f16.f32 "
                 "{%0,%1,%2,%3}, {%4,%5,%6,%7}, {%8,%9}, {%0,%1,%2,%3};"
                 : "+f"(d[0]), "+f"(d[1]), "+f"(d[2]), "+f"(d[3])
                 : "r"(a0), "r"(a1), "r"(a2), "r"(a3), "r"(b0), "r"(b1));
}
__device__ __forceinline__ uint32_t packh2(float a, float b) {
    __half2 h = __floats2half2_rn(a, b);
    return *(uint32_t*)&h;
}

// ---------------- kernel 1: head conv + weight prep (merged) ----------------
__global__ __launch_bounds__(256) void k_prep(const float* __restrict__ x,
                                              const float* __restrict__ w_head,
                                              const float* __restrict__ b_head,
                                              const float* __restrict__ w_dcn) {
    __shared__ float4 whf4[C_*9];     // [c][k] -> (w0,w1,w2,0)
    __shared__ float  win[8*324];

    int tid = threadIdx.x;
    int bx  = blockIdx.x;

    if (bx >= 144) {
        // ---- weight prep: t indexes [ci][sub][wm][mt][lane] ----
        int t = (bx - 144) * 256 + tid;     // 0..18431
        int lane = t & 31;
        int mt  = (t >> 5) & 3;
        int wm  = (t >> 7) & 1;
        int sub = (t >> 8) & 1;
        int ci  = t >> 9;                   // 0..35
        int cg = ci / 9, kk = ci % 9;
        int g = lane >> 2, tg = lane & 3;
        int o  = wm*64 + mt*16 + g;
        int c0 = cg*32 + sub*16 + 2*tg;
        uint4 u;
        u.x = packh2(w_dcn[o*1152 + c0*9 + kk],         w_dcn[o*1152 + (c0+1)*9 + kk]);
        u.y = packh2(w_dcn[(o+8)*1152 + c0*9 + kk],     w_dcn[(o+8)*1152 + (c0+1)*9 + kk]);
        u.z = packh2(w_dcn[o*1152 + (c0+8)*9 + kk],     w_dcn[o*1152 + (c0+9)*9 + kk]);
        u.w = packh2(w_dcn[(o+8)*1152 + (c0+8)*9 + kk], w_dcn[(o+8)*1152 + (c0+9)*9 + kk]);
        g_wA[t] = u;
        return;
    }

    // ---- head conv ----
    int n   = bx / 36;
    int t   = bx % 36;
    int by0 = (t / 6) * 16;
    int bx0 = (t % 6) * 16;

    for (int i = tid; i < C_*9; i += 256) {
        int c = i / 9, k = i % 9;
        whf4[i] = make_float4(w_head[(0*C_ + c)*9 + k],
                              w_head[(1*C_ + c)*9 + k],
                              w_head[(2*C_ + c)*9 + k], 0.f);
    }

    int ly = tid / 16, lx = tid % 16;
    float h0 = 0.f, h1 = 0.f, h2 = 0.f;

    for (int c0 = 0; c0 < C_; c0 += 8) {
        __syncthreads();
        for (int i = tid; i < 8*324; i += 256) {
            int cb = i / 324;
            int r  = (i % 324) / 18, cc = (i % 324) % 18;
            int gy = by0 - 1 + r, gx = bx0 - 1 + cc;
            float v = 0.f;
            if (gy >= 0 && gy < H_ && gx >= 0 && gx < W_)
                v = x[((n*C_ + c0 + cb)*H_ + gy)*W_ + gx];
            win[i] = v;
        }
        __syncthreads();
        #pragma unroll
        for (int cb = 0; cb < 8; cb++) {
            int c = c0 + cb;
            #pragma unroll
            for (int k = 0; k < 9; k++) {
                int ky = k / 3, kx = k % 3;
                float v = win[cb*324 + (ly + ky)*18 + lx + kx];
                float4 wv = whf4[c*9 + k];
                h0 += v * wv.x;
                h1 += v * wv.y;
                h2 += v * wv.z;
            }
        }
    }
    h0 += b_head[0]; h1 += b_head[1]; h2 += b_head[2];

    int gy = by0 + ly, gx = bx0 + lx;
    int pix = n*HW_ + gy*W_ + gx;
    g_dx[pix]   = 0.25f * tanhf(h0);
    g_dy[pix]   = 0.25f * tanhf(h1);
    g_mask[pix] = 1.f / (1.f + expf(-h2));
}

// ---------------- kernel 2: deformable sampling + fp16 warp-MMA GEMM ----------------
// grid: N*72 blocks, 256 threads (8 warps = 2 M-halves x 4 N-quarters).
// A staged via smem (LDG prefetched early); sampW + Asm double-buffered ->
// exactly one __syncthreads per tap.
__global__ __launch_bounds__(256, 2) void k_dcn(const float* __restrict__ x,
                                                float* __restrict__ out) {
    extern __shared__ char smem[];
    short*    bidx  = (short*)(smem + SM_BIDX);
    float4*   wgt   = (float4*)(smem + SM_WGT);
    float*    red   = (float*)(smem + SM_RED);
    __half2*  win2  = (__half2*)(smem + SM_WIN2);   // [c][r*20+x] = (v[x], v[x+1])
    uint32_t* sampBuf[2] = { (uint32_t*)(smem + SM_SAMP0), (uint32_t*)(smem + SM_SAMP1) };
    uint4*    asmBuf[2]  = { (uint4*)(smem + SM_ASM0),     (uint4*)(smem + SM_ASM1) };

    int tid = threadIdx.x, w = tid >> 5, lane = tid & 31;
    int g = lane >> 2, tg = lane & 3;
    int wm = w >> 2, ng = w & 3;
    int n0w = ng * 32;
    int bx = blockIdx.x;
    int n   = bx / NREG_;
    int reg = bx % NREG_;
    int ty0 = (reg / 6) * TILEH_;
    int tx0 = (reg % 6) * TILEW_;
    int wy0 = ty0 - 2, wx0 = tx0 - 2;

    // ---- bilinear tables: 128 px x 9 taps (mask folded) ----
    if (tid < 128) {
        int p  = tid;
        int ly = p >> 4, lx = p & 15;
        int gy = ty0 + ly, gx = tx0 + lx;
        int pix = n*HW_ + gy*W_ + gx;
        float dx = g_dx[pix], dy = g_dy[pix], m = g_mask[pix];
        const float syc[9] = {0,0,0, 1,0,-1, 1,1,-1};
        const float sxc[9] = {0,1,-1, 0,0,0, 1,-1,1};
        #pragma unroll
        for (int k = 0; k < 9; k++) {
            int ky = k / 3, kx = k % 3;
            float py = (float)(gy + ky - 1) + syc[k]*dx;
            float px = (float)(gx + kx - 1) + sxc[k]*dy;
            float fy0 = floorf(py), fx0 = floorf(px);
            int y0 = (int)fy0, x0 = (int)fx0;
            float fy = py - fy0, fx = px - fx0;
            float v00 = (y0   >= 0 && y0   < H_ && x0   >= 0 && x0   < W_) ? 1.f : 0.f;
            float v01 = (y0   >= 0 && y0   < H_ && x0+1 >= 0 && x0+1 < W_) ? 1.f : 0.f;
            float v10 = (y0+1 >= 0 && y0+1 < H_ && x0   >= 0 && x0   < W_) ? 1.f : 0.f;
            float v11 = (y0+1 >= 0 && y0+1 < H_ && x0+1 >= 0 && x0+1 < W_) ? 1.f : 0.f;
            float4 w4;
            w4.x = (1.f-fy)*(1.f-fx)*v00*m;
            w4.y = (1.f-fy)*fx      *v01*m;
            w4.z = fy      *(1.f-fx)*v10*m;
            w4.w = fy      *fx      *v11*m;
            int ly0 = min(max(y0 - wy0, 0), WR_-2);
            int lx0 = min(max(x0 - wx0, 0), WC_-2);
            bidx[k*128 + p] = (short)(ly0*WC_ + lx0);
            wgt[k*128 + p]  = w4;
        }
    }

    float acc[4][4][4];
    #pragma unroll
    for (int a = 0; a < 4; a++)
        #pragma unroll
        for (int b = 0; b < 4; b++)
            #pragma unroll
            for (int r = 0; r < 4; r++) acc[a][b][r] = 0.f;

    int sp  = tid & 127;                // sampling pixel
    int sc0 = (tid >> 7) * 16;          // sampling channel half (0 or 16)

    for (int cg = 0; cg < 4; cg++) {
        // win2 rewrite safe: all sampling of prev cg done before its last tap
        // barrier; post-barrier work reads only samp/Asm buffers.
        for (int i = tid; i < 32*WWORDS_; i += 256) {
            int c = i / WWORDS_;
            int rem = i % WWORDS_;
            int r = rem / WC_, xx = rem % WC_;
            int gy = wy0 + r, gx = wx0 + xx;
            float v0 = 0.f, v1 = 0.f;
            if (gy >= 0 && gy < H_) {
                const float* row = x + ((n*C_ + cg*32 + c)*H_ + gy)*W_;
                if (gx >= 0 && gx < W_)       v0 = row[gx];
                if (gx+1 >= 0 && gx+1 < W_)   v1 = row[gx+1];
            }
            win2[i] = __floats2half2_rn(v0, v1);
        }
        __syncthreads();

        for (int k = 0; k < 9; k++) {
            int ci = cg*9 + k;
            int b  = ci & 1;
            uint32_t* sampW = sampBuf[b];
            uint4*    AsmU  = asmBuf[b];

            // ---- prefetch A frags early (LDG latency hidden by sampling) ----
            const uint4* asrc = g_wA + ci*512;
            uint4 ar0 = asrc[tid];
            uint4 ar1 = asrc[tid + 256];

            // ---- sampling -> sampW[b] (fp16 pairs) ----
            {
                int base = bidx[k*128 + sp];
                float4 w4 = wgt[k*128 + sp];
                #pragma unroll
                for (int j = 0; j < 16; j += 2) {
                    int c = sc0 + j;
                    float2 c0a = __half22float2(win2[c*WWORDS_ + base]);
                    float2 c0b = __half22float2(win2[c*WWORDS_ + base + WC_]);
                    float s0 = w4.x*c0a.x + w4.y*c0a.y + w4.z*c0b.x + w4.w*c0b.y;
                    float2 c1a = __half22float2(win2[(c+1)*WWORDS_ + base]);
                    float2 c1b = __half22float2(win2[(c+1)*WWORDS_ + base + WC_]);
                    float s1 = w4.x*c1a.x + w4.y*c1a.y + w4.z*c1b.x + w4.w*c1b.y;
                    sampW[sp*SROW_ + (c >> 1)] = packh2(s0, s1);
                }
            }
            // ---- stage A frags ----
            AsmU[tid]       = ar0;
            AsmU[tid + 256] = ar1;
            __syncthreads();   // the ONLY barrier per tap

            // ---- MMA: 2 sub-chunks of 16 channels ----
            #pragma unroll
            for (int sub = 0; sub < 2; sub++) {
                uint4 a[4];
                #pragma unroll
                for (int mt = 0; mt < 4; mt++)
                    a[mt] = AsmU[sub*256 + wm*128 + mt*32 + lane];
                uint32_t b0[4], b1[4];
                #pragma unroll
                for (int nt = 0; nt < 4; nt++) {
                    int px = n0w + nt*8 + g;
                    b0[nt] = sampW[px*SROW_ + sub*8 + tg];
                    b1[nt] = sampW[px*SROW_ + sub*8 + tg + 4];
                }
                #pragma unroll
                for (int mt = 0; mt < 4; mt++)
                    #pragma unroll
                    for (int nt = 0; nt < 4; nt++)
                        mma16816(acc[mt][nt], a[mt].x, a[mt].y, a[mt].z, a[mt].w,
                                 b0[nt], b1[nt]);
            }
            // no trailing barrier: next tap uses the other buffers
        }
    }

    // ---- epilogue: stores + GN partials ----
    float s4[4] = {0,0,0,0}, q4[4] = {0,0,0,0};
    #pragma unroll
    for (int mt = 0; mt < 4; mt++) {
        int o1 = wm*64 + mt*16 + g;
        #pragma unroll
        for (int nt = 0; nt < 4; nt++) {
            int p  = n0w + nt*8 + 2*tg;
            int gy = ty0 + (p >> 4), gx = tx0 + (p & 15);
            float2 lo = make_float2(acc[mt][nt][0], acc[mt][nt][1]);
            float2 hi = make_float2(acc[mt][nt][2], acc[mt][nt][3]);
            *(float2*)&out[((n*COUT_ + o1    )*H_ + gy)*W_ + gx] = lo;
            *(float2*)&out[((n*COUT_ + o1 + 8)*H_ + gy)*W_ + gx] = hi;
            #pragma unroll
            for (int r = 0; r < 4; r++) {
                float v = acc[mt][nt][r];
                s4[mt] += v; q4[mt] += v*v;
            }
        }
    }
    #pragma unroll
    for (int mt = 0; mt < 4; mt++) {
        #pragma unroll
        for (int o = 16; o; o >>= 1) {
            s4[mt] += __shfl_xor_sync(0xFFFFFFFFu, s4[mt], o);
            q4[mt] += __shfl_xor_sync(0xFFFFFFFFu, q4[mt], o);
        }
    }
    if (lane == 0) {
        #pragma unroll
        for (int mt = 0; mt < 4; mt++) {
            red[w*4 + mt]      = s4[mt];
            red[32 + w*4 + mt] = q4[mt];
        }
    }
    __syncthreads();
    if (tid < 8) {                    // group gid = wm*4+mt
        int gwm = tid >> 2, gmt = tid & 3;
        float s = 0.f, q = 0.f;
        #pragma unroll
        for (int j = 0; j < 4; j++) {
            s += red[(gwm*4 + j)*4 + gmt];
            q += red[32 + (gwm*4 + j)*4 + gmt];
        }
        int base = (((n*GN_GROUPS_ + tid)*NREG_) + reg)*2;
        g_part[base + 0] = s;
        g_part[base + 1] = q;
    }
}

// ---------------- kernel 3: fused GN stats + normalize + affine + relu ----------------
// grid: 1152 blocks; each block covers 4096 consecutive floats (<=2 GN groups).
// Warps 0/1 redundantly reduce the 72 per-tile partials for those groups.
__global__ __launch_bounds__(256) void k_apply(float* __restrict__ out,
                                               const float* __restrict__ gamma,
                                               const float* __restrict__ beta) {
    __shared__ float sstat[4];   // meanA, rstdA, meanB, rstdB
    int tid = threadIdx.x, w = tid >> 5, lane = tid & 31;
    int bx = blockIdx.x;
    int fstart = bx * 4096;

    int cA = (fstart / HW_) % COUT_;
    int nA = fstart / (HW_*COUT_);
    int gidA = nA*GN_GROUPS_ + (cA >> 4);
    int fend = fstart + 4095;
    int cB = (fend / HW_) % COUT_;
    int nB = fend / (HW_*COUT_);
    int gidB = nB*GN_GROUPS_ + (cB >> 4);

    if (w < 2) {
        int gid = (w == 0) ? gidA : gidB;
        if (w == 0 || gidB != gidA) {
            float s = 0.f, q = 0.f;
            for (int i = lane; i < NREG_; i += 32) {
                s += g_part[(gid*NREG_ + i)*2 + 0];
                q += g_part[(gid*NREG_ + i)*2 + 1];
            }
            #pragma unroll
            for (int o = 16; o; o >>= 1) {
                s += __shfl_xor_sync(0xFFFFFFFFu, s, o);
                q += __shfl_xor_sync(0xFFFFFFFFu, q, o);
            }
            if (lane == 0) {
                float inv = 1.f / CNT_PER_GROUP_;
                float mean = s * inv;
                float var  = q * inv - mean*mean;
                sstat[w*2 + 0] = mean;
                sstat[w*2 + 1] = rsqrtf(var + GN_EPS_);
            }
        }
    }
    __syncthreads();

    #pragma unroll
    for (int u = 0; u < 4; u++) {
        int i4 = bx*1024 + u*256 + tid;
        int i = i4 * 4;
        int c = (i / HW_) % COUT_;
        int n = i / (HW_*COUT_);
        int gid = n*GN_GROUPS_ + (c >> 4);
        int sel = (gid == gidA) ? 0 : 2;
        float mean = sstat[sel + 0];
        float rstd = sstat[sel + 1];
        float sc = rstd * gamma[c];
        float sh = beta[c] - mean * sc;
        float4 v = ((float4*)out)[i4];
        v.x = fmaxf(v.x*sc + sh, 0.f);
        v.y = fmaxf(v.y*sc + sh, 0.f);
        v.z = fmaxf(v.z*sc + sh, 0.f);
        v.w = fmaxf(v.w*sc + sh, 0.f);
        ((float4*)out)[i4] = v;
    }
}

extern "C" void kernel_launch(void* const* d_in, const int* in_sizes, int n_in,
                              void* d_out, int out_size) {
    const float* x       = (const float*)d_in[0];
    const float* w_head  = (const float*)d_in[1];
    const float* b_head  = (const float*)d_in[2];
    const float* w_dcn   = (const float*)d_in[3];
    const float* gamma   = (const float*)d_in[4];
    const float* beta    = (const float*)d_in[5];
    float* out = (float*)d_out;

    cudaFuncSetAttribute(k_dcn, cudaFuncAttributeMaxDynamicSharedMemorySize, SM_TOT);

    k_prep<<<216, 256>>>(x, w_head, b_head, w_dcn);
    k_dcn<<<N_*NREG_, 256, SM_TOT>>>(x, out);
    k_apply<<<N_*COUT_*HW_/4096, 256>>>(out, gamma, beta);
}